// round 2
// baseline (speedup 1.0000x reference)
#include <cuda_runtime.h>
#include <cuda_bf16.h>

#define NN 50000
#define NE 600000
#define DIM 128
#define NR 8
#define NB 8
#define NG 256

// ---------------- static device scratch (no allocations allowed) ----------------
__device__ float g_W[NR * DIM * DIM];                    // per-layer combined weights
__device__ float g_Hall[(size_t)NN * NR * DIM];          // projected features, all relations (204.8 MB)
__device__ float g_hA[(size_t)NN * DIM];
__device__ float g_hB[(size_t)NN * DIM];
__device__ float g_gate[NN];
__device__ float g_gmax[NG];
__device__ float g_gsum[NG];
__device__ float g_read[NG * DIM];

// ---------------- W_r = sum_b comp[r,b] * bases[b] ----------------
__global__ void k_compw(const float* __restrict__ bases, const float* __restrict__ comp) {
    int idx = blockIdx.x * blockDim.x + threadIdx.x;     // NR*DIM*DIM = 131072
    if (idx >= NR * DIM * DIM) return;
    int r = idx / (DIM * DIM);
    int io = idx - r * (DIM * DIM);
    float s = 0.f;
#pragma unroll
    for (int b = 0; b < NB; b++)
        s = fmaf(comp[r * NB + b], bases[b * DIM * DIM + io], s);
    g_W[idx] = s;
}

// ---------------- GEMM: Hall[n, r, o] = (relu?)A[n,:] @ W[r,:,o] ----------------
// Tile: 128 (M) x 128 (N per relation) x 32 (K). 256 threads, 8x8 microtile.
__global__ __launch_bounds__(256, 2) void k_gemm(const float* __restrict__ Aext,
                                                 int whichA, int relu_in) {
    const float* __restrict__ A = (whichA == 0) ? Aext : (whichA == 1 ? g_hA : g_hB);
    constexpr int BM = 128, BN = 128, BK = 32, TM = 8, TN = 8;
    __shared__ float As[BK][BM + 4];
    __shared__ float Bs[BK][BN];

    const int r = blockIdx.y;
    const int m0 = blockIdx.x * BM;
    const float* __restrict__ B = g_W + (size_t)r * DIM * DIM;

    const int tid = threadIdx.x;
    const int tx = tid & 15, ty = tid >> 4;

    float acc[TM][TN];
#pragma unroll
    for (int i = 0; i < TM; i++)
#pragma unroll
        for (int j = 0; j < TN; j++) acc[i][j] = 0.f;

    for (int k0 = 0; k0 < DIM; k0 += BK) {
        // load A tile: 128 rows x 32 k = 1024 float4, 4 per thread; store transposed
#pragma unroll
        for (int i = 0; i < 4; i++) {
            int id = tid + i * 256;
            int row = id >> 3;               // 0..127
            int kc = (id & 7) * 4;           // 0..28
            float4 v = make_float4(0.f, 0.f, 0.f, 0.f);
            int gm = m0 + row;
            if (gm < NN) v = *(const float4*)(A + (size_t)gm * DIM + k0 + kc);
            if (relu_in) {
                v.x = fmaxf(v.x, 0.f); v.y = fmaxf(v.y, 0.f);
                v.z = fmaxf(v.z, 0.f); v.w = fmaxf(v.w, 0.f);
            }
            As[kc + 0][row] = v.x; As[kc + 1][row] = v.y;
            As[kc + 2][row] = v.z; As[kc + 3][row] = v.w;
        }
        // load B tile: 32 k-rows x 128 cols = 1024 float4
#pragma unroll
        for (int i = 0; i < 4; i++) {
            int id = tid + i * 256;
            int row = id >> 5;               // 0..31
            int col = (id & 31) * 4;
            *(float4*)&Bs[row][col] = *(const float4*)(B + (size_t)(k0 + row) * DIM + col);
        }
        __syncthreads();
#pragma unroll
        for (int k = 0; k < BK; k++) {
            float a[TM], b[TN];
            float4 a0 = *(const float4*)&As[k][ty * TM];
            float4 a1 = *(const float4*)&As[k][ty * TM + 4];
            a[0] = a0.x; a[1] = a0.y; a[2] = a0.z; a[3] = a0.w;
            a[4] = a1.x; a[5] = a1.y; a[6] = a1.z; a[7] = a1.w;
            float4 b0 = *(const float4*)&Bs[k][tx * TN];
            float4 b1 = *(const float4*)&Bs[k][tx * TN + 4];
            b[0] = b0.x; b[1] = b0.y; b[2] = b0.z; b[3] = b0.w;
            b[4] = b1.x; b[5] = b1.y; b[6] = b1.z; b[7] = b1.w;
#pragma unroll
            for (int i = 0; i < TM; i++)
#pragma unroll
                for (int j = 0; j < TN; j++)
                    acc[i][j] = fmaf(a[i], b[j], acc[i][j]);
        }
        __syncthreads();
    }
#pragma unroll
    for (int i = 0; i < TM; i++) {
        int gm = m0 + ty * TM + i;
        if (gm < NN) {
            float* cp = g_Hall + ((size_t)gm * NR + r) * DIM + tx * TN;
            *(float4*)(cp + 0) = make_float4(acc[i][0], acc[i][1], acc[i][2], acc[i][3]);
            *(float4*)(cp + 4) = make_float4(acc[i][4], acc[i][5], acc[i][6], acc[i][7]);
        }
    }
}

// ---------------- out[n,c] = bias[c] ----------------
__global__ void k_init(const float* __restrict__ bias, int whichOut) {
    float* out = (whichOut == 1) ? g_hA : g_hB;
    size_t idx = (size_t)blockIdx.x * blockDim.x + threadIdx.x;
    if (idx < (size_t)NN * DIM) out[idx] = bias[idx & (DIM - 1)];
}

// ---------------- scatter: out[dst] += Hall[src, etype] (warp per edge) ----------------
__global__ void k_scatter(const int* __restrict__ src, const int* __restrict__ dst,
                          const int* __restrict__ et, int whichOut) {
    float* out = (whichOut == 1) ? g_hA : g_hB;
    int e = blockIdx.x * 8 + (threadIdx.x >> 5);
    if (e >= NE) return;
    int lane = threadIdx.x & 31;
    int s = __ldg(src + e), d = __ldg(dst + e), r = __ldg(et + e);
    float4 v = ((const float4*)(g_Hall + ((size_t)s * NR + r) * DIM))[lane];
    float* o = out + (size_t)d * DIM + lane * 4;
    asm volatile("red.global.add.v4.f32 [%0], {%1,%2,%3,%4};"
                 :: "l"(o), "f"(v.x), "f"(v.y), "f"(v.z), "f"(v.w) : "memory");
}

// ---------------- pooling ----------------
__global__ void k_poolinit() {
    int idx = blockIdx.x * blockDim.x + threadIdx.x;
    if (idx < NG) { g_gmax[idx] = -__int_as_float(0x7f800000); g_gsum[idx] = 0.f; }
    if (idx < NG * DIM) g_read[idx] = 0.f;
}

__global__ void k_gate(const float* __restrict__ gw, const float* __restrict__ gb,
                       const int* __restrict__ n2g) {
    int n = blockIdx.x * 8 + (threadIdx.x >> 5);
    if (n >= NN) return;
    int lane = threadIdx.x & 31;
    float4 hv = ((const float4*)(g_hA + (size_t)n * DIM))[lane];
    float4 wv = ((const float4*)gw)[lane];
    float s = hv.x * wv.x + hv.y * wv.y + hv.z * wv.z + hv.w * wv.w;
#pragma unroll
    for (int o = 16; o; o >>= 1) s += __shfl_xor_sync(0xffffffffu, s, o);
    if (lane == 0) {
        s += gb[0];
        g_gate[n] = s;
        int g = n2g[n];
        int* ia = (int*)&g_gmax[g];
        int old = *ia;
        while (__int_as_float(old) < s) {
            int prev = atomicCAS(ia, old, __float_as_int(s));
            if (prev == old) break;
            old = prev;
        }
    }
}

__global__ void k_expsum(const int* __restrict__ n2g) {
    int n = blockIdx.x * blockDim.x + threadIdx.x;
    if (n >= NN) return;
    int g = n2g[n];
    float e = expf(g_gate[n] - g_gmax[g]);
    g_gate[n] = e;
    atomicAdd(&g_gsum[g], e);
}

__global__ void k_readout(const int* __restrict__ n2g) {
    int n = blockIdx.x * 8 + (threadIdx.x >> 5);
    if (n >= NN) return;
    int lane = threadIdx.x & 31;
    int g = n2g[n];
    float w = g_gate[n] / g_gsum[g];
    float4 hv = ((const float4*)(g_hA + (size_t)n * DIM))[lane];
    float* o = g_read + g * DIM + lane * 4;
    asm volatile("red.global.add.v4.f32 [%0], {%1,%2,%3,%4};"
                 :: "l"(o), "f"(hv.x * w), "f"(hv.y * w), "f"(hv.z * w), "f"(hv.w * w)
                 : "memory");
}

// ---------------- MLP head: relu(relu(r@fc1)@fc2)@fc3 -> sigmoid ----------------
__global__ void k_mlp(const float* __restrict__ fc1_w, const float* __restrict__ fc1_b,
                      const float* __restrict__ fc2_w, const float* __restrict__ fc2_b,
                      const float* __restrict__ fc3_w, const float* __restrict__ fc3_b,
                      float* __restrict__ out) {
    int g = blockIdx.x;
    int t = threadIdx.x;
    __shared__ float r[DIM];
    __shared__ float z1[100];
    __shared__ float z2[64];
    r[t] = g_read[g * DIM + t];
    __syncthreads();
    if (t < 100) {
        float s = fc1_b[t];
        for (int i = 0; i < DIM; i++) s = fmaf(r[i], fc1_w[i * 100 + t], s);
        z1[t] = fmaxf(s, 0.f);
    }
    __syncthreads();
    if (t < 64) {
        float s = fc2_b[t];
        for (int i = 0; i < 100; i++) s = fmaf(z1[i], fc2_w[i * 64 + t], s);
        z2[t] = fmaxf(s, 0.f);
    }
    __syncthreads();
    if (t == 0) {
        float s = fc3_b[0];
        for (int i = 0; i < 64; i++) s = fmaf(z2[i], fc3_w[i], s);
        out[g] = 1.f / (1.f + expf(-s));
    }
}

// ---------------- host launcher ----------------
extern "C" void kernel_launch(void* const* d_in, const int* in_sizes, int n_in,
                              void* d_out, int out_size) {
    const float *features, *bases1, *comp1, *bias1, *bases2, *comp2, *bias2;
    const float *bases3, *comp3, *bias3, *gate_w, *gate_b;
    const float *fc1_w, *fc1_b, *fc2_w, *fc2_b, *fc3_w, *fc3_b;
    const int *src, *dst, *etype, *n2g;

    if (in_sizes[1] == NE) {
        // setup_inputs dict order
        features = (const float*)d_in[0];
        src      = (const int*)d_in[1];
        dst      = (const int*)d_in[2];
        etype    = (const int*)d_in[3];
        n2g      = (const int*)d_in[4];
        bases1 = (const float*)d_in[5];  comp1 = (const float*)d_in[6];  bias1 = (const float*)d_in[7];
        bases2 = (const float*)d_in[8];  comp2 = (const float*)d_in[9];  bias2 = (const float*)d_in[10];
        bases3 = (const float*)d_in[11]; comp3 = (const float*)d_in[12]; bias3 = (const float*)d_in[13];
        gate_w = (const float*)d_in[14]; gate_b = (const float*)d_in[15];
        fc1_w = (const float*)d_in[16]; fc1_b = (const float*)d_in[17];
        fc2_w = (const float*)d_in[18]; fc2_b = (const float*)d_in[19];
        fc3_w = (const float*)d_in[20]; fc3_b = (const float*)d_in[21];
    } else {
        // reference() signature order
        features = (const float*)d_in[0];
        bases1 = (const float*)d_in[1];  comp1 = (const float*)d_in[2];  bias1 = (const float*)d_in[3];
        bases2 = (const float*)d_in[4];  comp2 = (const float*)d_in[5];  bias2 = (const float*)d_in[6];
        bases3 = (const float*)d_in[7];  comp3 = (const float*)d_in[8];  bias3 = (const float*)d_in[9];
        gate_w = (const float*)d_in[10]; gate_b = (const float*)d_in[11];
        fc1_w = (const float*)d_in[12]; fc1_b = (const float*)d_in[13];
        fc2_w = (const float*)d_in[14]; fc2_b = (const float*)d_in[15];
        fc3_w = (const float*)d_in[16]; fc3_b = (const float*)d_in[17];
        src   = (const int*)d_in[18];
        dst   = (const int*)d_in[19];
        etype = (const int*)d_in[20];
        n2g   = (const int*)d_in[21];
    }
    float* out = (float*)d_out;

    const dim3 gemm_grid((NN + 127) / 128, NR);
    const int init_blocks = (NN * DIM + 255) / 256;      // 25000
    const int scat_blocks = NE / 8;                      // 75000
    const int node_warp_blocks = NN / 8;                 // 6250

    // ---- layer 1: features -> g_hA
    k_compw<<<(NR * DIM * DIM + 255) / 256, 256>>>(bases1, comp1);
    k_gemm<<<gemm_grid, 256>>>(features, 0, 0);
    k_init<<<init_blocks, 256>>>(bias1, 1);
    k_scatter<<<scat_blocks, 256>>>(src, dst, etype, 1);
    // ---- layer 2: relu(g_hA) -> g_hB
    k_compw<<<(NR * DIM * DIM + 255) / 256, 256>>>(bases2, comp2);
    k_gemm<<<gemm_grid, 256>>>(features, 1, 1);
    k_init<<<init_blocks, 256>>>(bias2, 2);
    k_scatter<<<scat_blocks, 256>>>(src, dst, etype, 2);
    // ---- layer 3: relu(g_hB) -> g_hA
    k_compw<<<(NR * DIM * DIM + 255) / 256, 256>>>(bases3, comp3);
    k_gemm<<<gemm_grid, 256>>>(features, 2, 1);
    k_init<<<init_blocks, 256>>>(bias3, 1);
    k_scatter<<<scat_blocks, 256>>>(src, dst, etype, 1);
    // ---- attention pooling on g_hA
    k_poolinit<<<(NG * DIM + 255) / 256, 256>>>();
    k_gate<<<node_warp_blocks, 256>>>(gate_w, gate_b, n2g);
    k_expsum<<<(NN + 255) / 256, 256>>>(n2g);
    k_readout<<<node_warp_blocks, 256>>>(n2g);
    // ---- MLP head
    k_mlp<<<NG, DIM>>>(fc1_w, fc1_b, fc2_w, fc2_b, fc3_w, fc3_b, out);
}

// round 4
// speedup vs baseline: 1.4810x; 1.4810x over previous
#include <cuda_runtime.h>
#include <cuda_bf16.h>
#include <cstdint>

#define NN 50000
#define NE 600000
#define DIM 128
#define NR 8
#define NB 8
#define NG 256
#define KSPLIT 384   // [hi | lo | hi]

// ---------------- static device scratch ----------------
__device__ __nv_bfloat16 g_A2[(size_t)NN * KSPLIT];          // split input, 38.4MB
__device__ __nv_bfloat16 g_W2[NR * DIM * KSPLIT];            // split transposed weights
__device__ float g_Hall[(size_t)NN * NR * DIM];              // 204.8 MB
__device__ float g_hA[(size_t)NN * DIM];
__device__ float g_hB[(size_t)NN * DIM];
__device__ float g_gate[NN];
__device__ float g_gmax[NG];
__device__ float g_gsum[NG];
__device__ float g_read[NG * DIM];

// ---------------- PTX helpers (Ampere-class ISA only: safe on sm_103 target) ----------------
__device__ __forceinline__ uint32_t smem_u32(const void* p) {
    uint32_t a;
    asm("{ .reg .u64 t; cvta.to.shared.u64 t, %1; cvt.u32.u64 %0, t; }" : "=r"(a) : "l"(p));
    return a;
}
#define CP_ASYNC16(dst, src) \
    asm volatile("cp.async.cg.shared.global [%0], [%1], 16;" :: "r"(dst), "l"(src))
#define CP_COMMIT() asm volatile("cp.async.commit_group;" ::: "memory")
#define CP_WAIT0()  asm volatile("cp.async.wait_group 0;" ::: "memory")

#define LDMX4(f, addr) asm volatile( \
    "ldmatrix.sync.aligned.m8n8.x4.shared.b16 {%0,%1,%2,%3}, [%4];" \
    : "=r"((f)[0]), "=r"((f)[1]), "=r"((f)[2]), "=r"((f)[3]) : "r"(addr))

#define MMA_BF16(d, a, b0, b1) asm volatile( \
    "mma.sync.aligned.m16n8k16.row.col.f32.bf16.bf16.f32 " \
    "{%0,%1,%2,%3}, {%4,%5,%6,%7}, {%8,%9}, {%0,%1,%2,%3};" \
    : "+f"((d)[0]), "+f"((d)[1]), "+f"((d)[2]), "+f"((d)[3]) \
    : "r"((a)[0]), "r"((a)[1]), "r"((a)[2]), "r"((a)[3]), "r"(b0), "r"(b1))

// ---------------- split weights: W2[r][n][k*] = hi/hi/lo of (comp@bases)^T ----------------
__global__ void k_splitw(const float* __restrict__ bases, const float* __restrict__ comp) {
    int r = blockIdx.y;
    int t = blockIdx.x * 256 + threadIdx.x;              // 0..16383
    if (t >= DIM * DIM) return;
    int k = t >> 7, n = t & 127;
    float s = 0.f;
#pragma unroll
    for (int b = 0; b < NB; b++)
        s = fmaf(comp[r * NB + b], bases[((size_t)b * DIM + k) * DIM + n], s);
    __nv_bfloat16 hi = __float2bfloat16(s);
    __nv_bfloat16 lo = __float2bfloat16(s - __bfloat162float(hi));
    __nv_bfloat16* w = g_W2 + ((size_t)r * DIM + n) * KSPLIT;
    w[k] = hi; w[128 + k] = hi; w[256 + k] = lo;
}

// ---------------- split activations: A2[n] = [hi | lo | hi] of (relu?) x[n] ----------------
__global__ void k_split(const float* __restrict__ Aext, int whichA, int relu_in) {
    const float* __restrict__ A = (whichA == 0) ? Aext : (whichA == 1 ? g_hA : g_hB);
    size_t idx = (size_t)blockIdx.x * blockDim.x + threadIdx.x;   // NN*32
    if (idx >= (size_t)NN * 32) return;
    size_t n = idx >> 5;
    int c4 = (int)(idx & 31);
    float4 v = ((const float4*)(A + n * DIM))[c4];
    if (relu_in) {
        v.x = fmaxf(v.x, 0.f); v.y = fmaxf(v.y, 0.f);
        v.z = fmaxf(v.z, 0.f); v.w = fmaxf(v.w, 0.f);
    }
    __nv_bfloat16 h[4], l[4];
    float f[4] = {v.x, v.y, v.z, v.w};
#pragma unroll
    for (int i = 0; i < 4; i++) {
        h[i] = __float2bfloat16(f[i]);
        l[i] = __float2bfloat16(f[i] - __bfloat162float(h[i]));
    }
    uint2 hp = *(uint2*)h, lp = *(uint2*)l;
    __nv_bfloat16* a2 = g_A2 + n * KSPLIT + c4 * 4;
    *(uint2*)(a2)        = hp;
    *(uint2*)(a2 + 128)  = lp;
    *(uint2*)(a2 + 256)  = hp;
}

// ---------------- HMMA GEMM: Hall[n,r,:] = A2[n,:] @ W2[r,:,:]^T ----------------
// CTA: 128(M) x 128(N), one relation per blockIdx.y. 8 warps, warp tile 32x64.
// BK=64 per chunk via cp.async; smem rows padded to 72 bf16 (conflict-free ldmatrix).
__global__ __launch_bounds__(256, 2) void k_gemm_mma() {
    constexpr int SP = 72;                                // bf16 per smem row
    __shared__ __nv_bfloat16 sA[128 * SP];
    __shared__ __nv_bfloat16 sB[128 * SP];

    const int tid = threadIdx.x;
    const int wid = tid >> 5, lane = tid & 31;
    const int r = blockIdx.y;
    const int m0 = blockIdx.x * 128;
    const int wm = (wid & 3) * 32;                        // warp M offset in tile
    const int wn = (wid >> 2) * 64;                       // warp N offset in tile

    const __nv_bfloat16* __restrict__ Ag = g_A2;
    const __nv_bfloat16* __restrict__ Bg = g_W2 + (size_t)r * DIM * KSPLIT;

    float acc[2][8][4];
#pragma unroll
    for (int mi = 0; mi < 2; mi++)
#pragma unroll
        for (int ni = 0; ni < 8; ni++)
#pragma unroll
            for (int q = 0; q < 4; q++) acc[mi][ni][q] = 0.f;

    const uint32_t sA_b = smem_u32(sA), sB_b = smem_u32(sB);

    // per-lane ldmatrix row/col offsets (same pattern for A and B)
    const int lrow = (lane & 7) + ((lane & 8) ? 8 : 0);   // row within 16-row tile
    const int lcol = (lane & 16) ? 8 : 0;                 // k half

    for (int kc = 0; kc < 6; kc++) {
        // stage chunk: 128 rows x 64 bf16 each for A and B (4 x 16B per thread each)
#pragma unroll
        for (int i = 0; i < 4; i++) {
            int id = tid + i * 256;
            int row = id >> 3, seg = id & 7;
            int gr = m0 + row; if (gr >= NN) gr = NN - 1;
            CP_ASYNC16(sA_b + (row * SP + seg * 8) * 2,
                       Ag + (size_t)gr * KSPLIT + kc * 64 + seg * 8);
            CP_ASYNC16(sB_b + (row * SP + seg * 8) * 2,
                       Bg + (size_t)row * KSPLIT + kc * 64 + seg * 8);
        }
        CP_COMMIT(); CP_WAIT0();
        __syncthreads();

#pragma unroll
        for (int ks = 0; ks < 4; ks++) {
            const int k0 = ks * 16;
            uint32_t aF[2][4], bF[4][4];
#pragma unroll
            for (int mi = 0; mi < 2; mi++) {
                uint32_t addr = sA_b + ((wm + mi * 16 + lrow) * SP + k0 + lcol) * 2;
                LDMX4(aF[mi], addr);
            }
#pragma unroll
            for (int g = 0; g < 4; g++) {
                uint32_t addr = sB_b + ((wn + g * 16 + lrow) * SP + k0 + lcol) * 2;
                LDMX4(bF[g], addr);
            }
#pragma unroll
            for (int mi = 0; mi < 2; mi++)
#pragma unroll
                for (int ni = 0; ni < 8; ni++) {
                    uint32_t b0 = bF[ni >> 1][(ni & 1)];
                    uint32_t b1 = bF[ni >> 1][(ni & 1) + 2];
                    MMA_BF16(acc[mi][ni], aF[mi], b0, b1);
                }
        }
        __syncthreads();
    }

    // epilogue: c-frag mapping row=lane>>2 (+8), col=(lane&3)*2 (+1)
#pragma unroll
    for (int mi = 0; mi < 2; mi++) {
        int row0 = m0 + wm + mi * 16 + (lane >> 2);
#pragma unroll
        for (int half = 0; half < 2; half++) {
            int gr = row0 + half * 8;
            if (gr < NN) {
                float* base = g_Hall + ((size_t)gr * NR + r) * DIM + wn + (lane & 3) * 2;
#pragma unroll
                for (int ni = 0; ni < 8; ni++)
                    *(float2*)(base + ni * 8) =
                        make_float2(acc[mi][ni][half * 2], acc[mi][ni][half * 2 + 1]);
            }
        }
    }
}

// ---------------- out[n,c] = bias[c] ----------------
__global__ void k_init(const float* __restrict__ bias, int whichOut) {
    float* out = (whichOut == 1) ? g_hA : g_hB;
    size_t idx = (size_t)blockIdx.x * blockDim.x + threadIdx.x;
    if (idx < (size_t)NN * DIM) out[idx] = bias[idx & (DIM - 1)];
}

// ---------------- scatter: out[dst] += Hall[src, etype] ----------------
__global__ void k_scatter(const int* __restrict__ src, const int* __restrict__ dst,
                          const int* __restrict__ et, int whichOut) {
    float* out = (whichOut == 1) ? g_hA : g_hB;
    int e = blockIdx.x * 8 + (threadIdx.x >> 5);
    if (e >= NE) return;
    int lane = threadIdx.x & 31;
    int s = __ldg(src + e), d = __ldg(dst + e), r = __ldg(et + e);
    float4 v = ((const float4*)(g_Hall + ((size_t)s * NR + r) * DIM))[lane];
    float* o = out + (size_t)d * DIM + lane * 4;
    asm volatile("red.global.add.v4.f32 [%0], {%1,%2,%3,%4};"
                 :: "l"(o), "f"(v.x), "f"(v.y), "f"(v.z), "f"(v.w) : "memory");
}

// ---------------- pooling ----------------
__global__ void k_poolinit() {
    int idx = blockIdx.x * blockDim.x + threadIdx.x;
    if (idx < NG) { g_gmax[idx] = -__int_as_float(0x7f800000); g_gsum[idx] = 0.f; }
    if (idx < NG * DIM) g_read[idx] = 0.f;
}

__global__ void k_gate(const float* __restrict__ gw, const float* __restrict__ gb,
                       const int* __restrict__ n2g) {
    int n = blockIdx.x * 8 + (threadIdx.x >> 5);
    if (n >= NN) return;
    int lane = threadIdx.x & 31;
    float4 hv = ((const float4*)(g_hA + (size_t)n * DIM))[lane];
    float4 wv = ((const float4*)gw)[lane];
    float s = hv.x * wv.x + hv.y * wv.y + hv.z * wv.z + hv.w * wv.w;
#pragma unroll
    for (int o = 16; o; o >>= 1) s += __shfl_xor_sync(0xffffffffu, s, o);
    if (lane == 0) {
        s += gb[0];
        g_gate[n] = s;
        int g = n2g[n];
        int* ia = (int*)&g_gmax[g];
        int old = *ia;
        while (__int_as_float(old) < s) {
            int prev = atomicCAS(ia, old, __float_as_int(s));
            if (prev == old) break;
            old = prev;
        }
    }
}

__global__ void k_expsum(const int* __restrict__ n2g) {
    int n = blockIdx.x * blockDim.x + threadIdx.x;
    if (n >= NN) return;
    int g = n2g[n];
    float e = expf(g_gate[n] - g_gmax[g]);
    g_gate[n] = e;
    atomicAdd(&g_gsum[g], e);
}

__global__ void k_readout(const int* __restrict__ n2g) {
    int n = blockIdx.x * 8 + (threadIdx.x >> 5);
    if (n >= NN) return;
    int lane = threadIdx.x & 31;
    int g = n2g[n];
    float w = g_gate[n] / g_gsum[g];
    float4 hv = ((const float4*)(g_hA + (size_t)n * DIM))[lane];
    float* o = g_read + g * DIM + lane * 4;
    asm volatile("red.global.add.v4.f32 [%0], {%1,%2,%3,%4};"
                 :: "l"(o), "f"(hv.x * w), "f"(hv.y * w), "f"(hv.z * w), "f"(hv.w * w)
                 : "memory");
}

// ---------------- MLP head ----------------
__global__ void k_mlp(const float* __restrict__ fc1_w, const float* __restrict__ fc1_b,
                      const float* __restrict__ fc2_w, const float* __restrict__ fc2_b,
                      const float* __restrict__ fc3_w, const float* __restrict__ fc3_b,
                      float* __restrict__ out) {
    int g = blockIdx.x;
    int t = threadIdx.x;
    __shared__ float r[DIM];
    __shared__ float z1[100];
    __shared__ float z2[64];
    r[t] = g_read[g * DIM + t];
    __syncthreads();
    if (t < 100) {
        float s = fc1_b[t];
        for (int i = 0; i < DIM; i++) s = fmaf(r[i], fc1_w[i * 100 + t], s);
        z1[t] = fmaxf(s, 0.f);
    }
    __syncthreads();
    if (t < 64) {
        float s = fc2_b[t];
        for (int i = 0; i < 100; i++) s = fmaf(z1[i], fc2_w[i * 64 + t], s);
        z2[t] = fmaxf(s, 0.f);
    }
    __syncthreads();
    if (t == 0) {
        float s = fc3_b[0];
        for (int i = 0; i < 64; i++) s = fmaf(z2[i], fc3_w[i], s);
        out[g] = 1.f / (1.f + expf(-s));
    }
}

// ---------------- host launcher ----------------
extern "C" void kernel_launch(void* const* d_in, const int* in_sizes, int n_in,
                              void* d_out, int out_size) {
    const float *features, *bases1, *comp1, *bias1, *bases2, *comp2, *bias2;
    const float *bases3, *comp3, *bias3, *gate_w, *gate_b;
    const float *fc1_w, *fc1_b, *fc2_w, *fc2_b, *fc3_w, *fc3_b;
    const int *src, *dst, *etype, *n2g;

    if (in_sizes[1] == NE) {
        features = (const float*)d_in[0];
        src      = (const int*)d_in[1];
        dst      = (const int*)d_in[2];
        etype    = (const int*)d_in[3];
        n2g      = (const int*)d_in[4];
        bases1 = (const float*)d_in[5];  comp1 = (const float*)d_in[6];  bias1 = (const float*)d_in[7];
        bases2 = (const float*)d_in[8];  comp2 = (const float*)d_in[9];  bias2 = (const float*)d_in[10];
        bases3 = (const float*)d_in[11]; comp3 = (const float*)d_in[12]; bias3 = (const float*)d_in[13];
        gate_w = (const float*)d_in[14]; gate_b = (const float*)d_in[15];
        fc1_w = (const float*)d_in[16]; fc1_b = (const float*)d_in[17];
        fc2_w = (const float*)d_in[18]; fc2_b = (const float*)d_in[19];
        fc3_w = (const float*)d_in[20]; fc3_b = (const float*)d_in[21];
    } else {
        features = (const float*)d_in[0];
        bases1 = (const float*)d_in[1];  comp1 = (const float*)d_in[2];  bias1 = (const float*)d_in[3];
        bases2 = (const float*)d_in[4];  comp2 = (const float*)d_in[5];  bias2 = (const float*)d_in[6];
        bases3 = (const float*)d_in[7];  comp3 = (const float*)d_in[8];  bias3 = (const float*)d_in[9];
        gate_w = (const float*)d_in[10]; gate_b = (const float*)d_in[11];
        fc1_w = (const float*)d_in[12]; fc1_b = (const float*)d_in[13];
        fc2_w = (const float*)d_in[14]; fc2_b = (const float*)d_in[15];
        fc3_w = (const float*)d_in[16]; fc3_b = (const float*)d_in[17];
        src   = (const int*)d_in[18];
        dst   = (const int*)d_in[19];
        etype = (const int*)d_in[20];
        n2g   = (const int*)d_in[21];
    }
    float* out = (float*)d_out;

    const dim3 gemm_grid((NN + 127) / 128, NR);          // 391 x 8
    const dim3 splitw_grid(64, NR);
    const int split_blocks = (NN * 32 + 255) / 256;      // 6250
    const int init_blocks = (NN * DIM + 255) / 256;
    const int scat_blocks = NE / 8;
    const int node_warp_blocks = NN / 8;

    // ---- layer 1: features -> g_hA
    k_splitw<<<splitw_grid, 256>>>(bases1, comp1);
    k_split<<<split_blocks, 256>>>(features, 0, 0);
    k_gemm_mma<<<gemm_grid, 256>>>();
    k_init<<<init_blocks, 256>>>(bias1, 1);
    k_scatter<<<scat_blocks, 256>>>(src, dst, etype, 1);
    // ---- layer 2: relu(g_hA) -> g_hB
    k_splitw<<<splitw_grid, 256>>>(bases2, comp2);
    k_split<<<split_blocks, 256>>>(features, 1, 1);
    k_gemm_mma<<<gemm_grid, 256>>>();
    k_init<<<init_blocks, 256>>>(bias2, 2);
    k_scatter<<<scat_blocks, 256>>>(src, dst, etype, 2);
    // ---- layer 3: relu(g_hB) -> g_hA
    k_splitw<<<splitw_grid, 256>>>(bases3, comp3);
    k_split<<<split_blocks, 256>>>(features, 2, 1);
    k_gemm_mma<<<gemm_grid, 256>>>();
    k_init<<<init_blocks, 256>>>(bias3, 1);
    k_scatter<<<scat_blocks, 256>>>(src, dst, etype, 1);
    // ---- attention pooling on g_hA
    k_poolinit<<<(NG * DIM + 255) / 256, 256>>>();
    k_gate<<<node_warp_blocks, 256>>>(gate_w, gate_b, n2g);
    k_expsum<<<(NN + 255) / 256, 256>>>(n2g);
    k_readout<<<node_warp_blocks, 256>>>(n2g);
    // ---- MLP head
    k_mlp<<<NG, DIM>>>(fc1_w, fc1_b, fc2_w, fc2_b, fc3_w, fc3_b, out);
}